// round 9
// baseline (speedup 1.0000x reference)
#include <cuda_runtime.h>

// Math collapse (verified passing in R8): softmax over a size-1 axis == 1.0, so
//   out[b,c,f] = sum_t x[b,t,f]    (context/W/b are dead inputs).
// Pure DRAM-bound: 32MB read + 16MB write -> ~6.5us floor at ~7.4TB/s.
//
// R8 ncu showed occ=20.5%, DRAM=33.9% -> latency-bound, not BW-bound.
// Fix: 4x more threads (1024 CTAs x 256), 8 batched loads/thread (MLP>=4),
// shfl_xor reduction across t-groups (t-group index sits in lane bits [2:5]).

#define B_ 32
#define T_ 512
#define C_ 256
#define F_ 512

static constexpr int F4      = F_ / 4;         // 128 float4 per row
static constexpr int TILE_F4 = 4;              // 16 floats per f-tile
static constexpr int NTILES  = F4 / TILE_F4;   // 32 tiles
static constexpr int TG      = 64;             // t-groups per block
static constexpr int TPB     = TILE_F4 * TG;   // 256 threads
static constexpr int T_PER   = T_ / TG;        // 8 timesteps per thread
static constexpr int NWARPS  = TPB / 32;       // 8

__device__ __forceinline__ void f4add(float4& a, const float4& b) {
    a.x += b.x; a.y += b.y; a.z += b.z; a.w += b.w;
}

__global__ __launch_bounds__(TPB)
void attn_collapse_v2(const float* __restrict__ x, float* __restrict__ out) {
    const int blk  = blockIdx.x;               // 0 .. B_*NTILES-1
    const int b    = blk / NTILES;
    const int tile = blk % NTILES;
    const int f4l  = threadIdx.x & (TILE_F4 - 1);   // lane bits [0:2)
    const int tg   = threadIdx.x >> 2;               // t-group: bits [2:8)
    const int f4   = tile * TILE_F4 + f4l;

    const float4* xb = reinterpret_cast<const float4*>(x)
                     + (size_t)b * T_ * F4 + f4;
    const size_t base = (size_t)(tg * T_PER) * F4;

    // --- 8 loads, batched 4-at-a-time so >=4 LDG.128 are always in flight ---
    float4 v0 = __ldg(&xb[base + 0 * F4]);
    float4 v1 = __ldg(&xb[base + 1 * F4]);
    float4 v2 = __ldg(&xb[base + 2 * F4]);
    float4 v3 = __ldg(&xb[base + 3 * F4]);
    float4 v4 = __ldg(&xb[base + 4 * F4]);
    float4 v5 = __ldg(&xb[base + 5 * F4]);
    float4 v6 = __ldg(&xb[base + 6 * F4]);
    float4 v7 = __ldg(&xb[base + 7 * F4]);
    f4add(v0, v4); f4add(v1, v5); f4add(v2, v6); f4add(v3, v7);
    f4add(v0, v2); f4add(v1, v3);
    f4add(v0, v1);
    float4 acc = v0;

    // --- reduce across the 8 t-groups inside each warp (lane bits 2,3,4) ---
#pragma unroll
    for (int off = 4; off < 32; off <<= 1) {
        acc.x += __shfl_xor_sync(0xffffffffu, acc.x, off);
        acc.y += __shfl_xor_sync(0xffffffffu, acc.y, off);
        acc.z += __shfl_xor_sync(0xffffffffu, acc.z, off);
        acc.w += __shfl_xor_sync(0xffffffffu, acc.w, off);
    }
    // every lane now holds its warp's partial for column f4l

    // --- combine the 8 warps via smem ---
    __shared__ float4 s[NWARPS][TILE_F4];
    const int wid = threadIdx.x >> 5;
    const int lid = threadIdx.x & 31;
    if (lid < TILE_F4) s[wid][lid] = acc;
    __syncthreads();
    if (threadIdx.x < TILE_F4) {
        float4 m = s[0][threadIdx.x];
#pragma unroll
        for (int w = 1; w < NWARPS; ++w) f4add(m, s[w][threadIdx.x]);
        s[0][threadIdx.x] = m;
    }
    __syncthreads();
    const float4 sum = s[0][f4l];   // final column sum for (b, f4)

    // --- broadcast across C: block owns a [C_, TILE_F4] float4 window ---
    // idx & 3 == f4l (256 ≡ 0 mod 4), so each thread writes its own column.
    float4* ob = reinterpret_cast<float4*>(out)
               + (size_t)b * C_ * F4 + tile * TILE_F4;
#pragma unroll
    for (int k = 0; k < (C_ * TILE_F4) / TPB; ++k) {
        const int idx = (k << 8) + threadIdx.x;        // 0..1023
        ob[(size_t)(idx >> 2) * F4 + (idx & 3)] = sum;
    }
}

extern "C" void kernel_launch(void* const* d_in, const int* in_sizes, int n_in,
                              void* d_out, int out_size) {
    (void)in_sizes; (void)n_in; (void)out_size;
    const float* x = (const float*)d_in[0];   // [B,T,F]; context/W/b dead
    float* out = (float*)d_out;               // [B,C,F]
    attn_collapse_v2<<<B_ * NTILES, TPB>>>(x, out);
}